// round 5
// baseline (speedup 1.0000x reference)
#include <cuda_runtime.h>
#include <math.h>

#define BB    16
#define TT    3300
#define FEAT  80
#define NC    512
#define RNN   512
#define G3    1536
#define DIN   592
#define NBLK  128   // persistent GRU blocks

typedef unsigned long long ull;

// ---------------- device scratch (no allocation allowed) ----------------
__device__ float    g_melsup[(size_t)BB * TT * FEAT];     // [b][t][f]
__device__ float    g_wohT[(size_t)NC * G3];              // [class][gate-row]
__device__ float    g_xproj[(size_t)TT * G3 * BB];        // [t][row][b] (includes b_ih)
__device__ float    g_hs[(size_t)BB * TT * RNN];          // GRU outputs
__device__ float    g_h1[(size_t)BB * TT * RNN];          // fc1 output
__device__ float    g_hbuf[2][BB * RNN];                  // ping-pong hidden state
__device__ unsigned g_cnt;                                // barrier counter

__device__ __forceinline__ float sigm(float x) { return 1.f / (1.f + __expf(-x)); }

// packed fp32x2 helpers (FFMA2 path — PTX-only, see SASS_QUICKREF)
__device__ __forceinline__ ull ffma2(ull a, ull b, ull c) {
    ull d;
    asm("fma.rn.f32x2 %0, %1, %2, %3;" : "=l"(d) : "l"(a), "l"(b), "l"(c));
    return d;
}
__device__ __forceinline__ ull pack2(float x, float y) {
    float2 f = make_float2(x, y);
    return *reinterpret_cast<ull*>(&f);
}
__device__ __forceinline__ float hsum2(ull v) {
    float2 f = *reinterpret_cast<float2*>(&v);
    return f.x + f.y;
}

// ---------------- init ----------------
__global__ void k_init() {
    int i = blockIdx.x * 256 + threadIdx.x;
    if (i < 2 * BB * RNN) ((float*)g_hbuf)[i] = 0.f;
    if (i == 0) g_cnt = 0u;
}

// ---------------- transpose one-hot table: wohT[c][g] = w_ih[g][c] ----------------
__global__ void k_woh(const float* __restrict__ w_ih) {
    int idx = blockIdx.x * 256 + threadIdx.x;
    if (idx >= NC * G3) return;
    int g = idx % G3, c = idx / G3;
    g_wohT[(size_t)c * G3 + g] = __ldg(&w_ih[(size_t)g * DIN + c]);
}

// ---------------- mel upsample: one block per (b,f) ----------------
__global__ void k_upsample(const float* __restrict__ mels,
                           const float* __restrict__ k0,
                           const float* __restrict__ k1,
                           const float* __restrict__ k2) {
    int bf = blockIdx.x;
    int b = bf / FEAT, f = bf % FEAT;
    __shared__ float s0[16], s1[80], s2[400], c0[11], c1[11], c2[23];
    int tid = threadIdx.x;
    if (tid < 16) s0[tid] = mels[((size_t)b * FEAT + f) * 16 + tid];
    if (tid < 11) c0[tid] = k0[tid];
    if (tid < 11) c1[tid] = k1[tid];
    if (tid < 23) c2[tid] = k2[tid];
    __syncthreads();
    if (tid < 80) {
        float a = 0.f;
        #pragma unroll
        for (int u = 0; u < 11; u++) {
            int p = tid + u - 5;
            if (p >= 0 && p < 80) a += c0[u] * s0[p / 5];
        }
        s1[tid] = a;
    }
    __syncthreads();
    if (tid < 400) {
        float a = 0.f;
        #pragma unroll
        for (int u = 0; u < 11; u++) {
            int p = tid + u - 5;
            if (p >= 0 && p < 400) a += c1[u] * s1[p / 5];
        }
        s2[tid] = a;
    }
    __syncthreads();
    for (int i = tid; i < TT; i += blockDim.x) {
        int p = i + 550;
        float a = 0.f;
        #pragma unroll
        for (int u = 0; u < 23; u++) a += c2[u] * s2[(p + u - 11) / 11];
        g_melsup[((size_t)b * TT + i) * FEAT + f] = a;
    }
}

// ---------------- x_proj precompute: one block per 4 timesteps ----------------
// xp[t][row][b] = wohT[x[b][t]][row] + b_ih[row] + sum_f mel[b][t][f]*w_ih[row][512+f]
// w-row held in registers across 4t*16b; f-paired FFMA2.
__global__ void __launch_bounds__(256) k_xproj(const int* __restrict__ x,
                                               const float* __restrict__ w_ih,
                                               const float* __restrict__ b_ih) {
    int t0 = blockIdx.x * 4;
    int tid = threadIdx.x;
    __shared__ float mel_s[4][BB][FEAT];   // 20 KB
    __shared__ int   cls_s[4][BB];

    // stage mels (vectorized): 1280 float4
    #pragma unroll
    for (int k = 0; k < 5; k++) {
        int f4 = tid + 256 * k;            // < 1280
        int tt = f4 / 320, rem = f4 % 320;
        int b = rem / 20, fq = rem % 20;
        *(float4*)&mel_s[tt][b][4 * fq] =
            *(const float4*)&g_melsup[((size_t)b * TT + t0 + tt) * FEAT + 4 * fq];
    }
    if (tid < 64) cls_s[tid >> 4][tid & 15] = x[(size_t)(tid & 15) * TT + t0 + (tid >> 4)];
    __syncthreads();

    #pragma unroll
    for (int rr = 0; rr < 6; rr++) {
        int r = 256 * rr + tid;            // 0..1535
        float4 w4[20];
        const float4* wrow = (const float4*)&w_ih[(size_t)r * DIN + NC];
        #pragma unroll
        for (int i = 0; i < 20; i++) w4[i] = __ldg(wrow + i);
        float bi = b_ih[r];

        #pragma unroll
        for (int tt = 0; tt < 4; tt++) {
            float outv[BB];
            #pragma unroll
            for (int b = 0; b < BB; b++) {
                ull acc = 0ull;
                #pragma unroll
                for (int i = 0; i < 20; i++) {
                    float4 m = *(const float4*)&mel_s[tt][b][4 * i];
                    ull m01 = *(ull*)&m.x, m23 = *(ull*)&m.z;
                    ull w01 = *(ull*)&w4[i].x, w23 = *(ull*)&w4[i].z;
                    acc = ffma2(w01, m01, acc);
                    acc = ffma2(w23, m23, acc);
                }
                outv[b] = hsum2(acc) + bi + g_wohT[(size_t)cls_s[tt][b] * G3 + r];
            }
            float* dst = &g_xproj[((size_t)(t0 + tt) * G3 + r) * BB];
            #pragma unroll
            for (int q = 0; q < 4; q++)
                *(float4*)&dst[4 * q] = make_float4(outv[4*q], outv[4*q+1], outv[4*q+2], outv[4*q+3]);
        }
    }
}

// ---------------- persistent GRU kernel ----------------
// 128 blocks x 256 thr; block owns 4 hidden units (12 gate-rows).
// Warp = (rowhalf rh: 6 rows) x (batchquad bq: 4 batches). w register-resident as f32x2.
__global__ void __launch_bounds__(256, 1) k_gru(const float* __restrict__ w_hh,
                                                const float* __restrict__ b_hh) {
    int bk = blockIdx.x;
    int j0 = bk * 4;
    int tid = threadIdx.x;
    int wi = tid >> 5, lane = tid & 31;
    int rh = wi & 1;                      // rows rh*6 .. rh*6+5
    int bq = wi >> 1;                     // batches bq*4 .. bq*4+3

    ull   w2[6][8];
    float bhh_[6];
    #pragma unroll
    for (int q = 0; q < 6; q++) {
        int lr = rh * 6 + q;              // linear row 0..11 = gate*4 + unit
        int g = lr >> 2, u = lr & 3;
        int row = g * RNN + j0 + u;
        bhh_[q] = b_hh[row];
        #pragma unroll
        for (int i = 0; i < 4; i++) {
            float4 v = *(const float4*)&w_hh[(size_t)row * RNN + i * 128 + 4 * lane];
            w2[q][2*i]   = pack2(v.x, v.y);
            w2[q][2*i+1] = pack2(v.z, v.w);
        }
    }

    __shared__ float h_s[BB][RNN];        // 32 KB
    __shared__ float y_s[12][BB];
    __shared__ float xp_s[12][BB];

    int cur = 0;
    for (int t = 0; t < TT; t++) {
        if (tid < 192) {                  // stage x_proj (12 rows x 16 b)
            int lr = tid >> 4, b = tid & 15;
            int g = lr >> 2, u = lr & 3;
            int row = g * RNN + j0 + u;
            xp_s[lr][b] = g_xproj[((size_t)t * G3 + row) * BB + b];
        }
        {                                 // stage h (L1-bypass: written by other SMs)
            const float4* src = (const float4*)g_hbuf[cur];
            float4* dst = (float4*)&h_s[0][0];
            #pragma unroll
            for (int i = 0; i < 8; i++) dst[tid + 256 * i] = __ldcg(src + tid + 256 * i);
        }
        __syncthreads();

        #pragma unroll
        for (int bi = 0; bi < 4; bi++) {
            int b = bq * 4 + bi;
            float4 h0 = *(const float4*)&h_s[b][0   + 4 * lane];
            float4 h1 = *(const float4*)&h_s[b][128 + 4 * lane];
            float4 h2 = *(const float4*)&h_s[b][256 + 4 * lane];
            float4 h3 = *(const float4*)&h_s[b][384 + 4 * lane];
            ull hh[8];
            hh[0] = *(ull*)&h0.x; hh[1] = *(ull*)&h0.z;
            hh[2] = *(ull*)&h1.x; hh[3] = *(ull*)&h1.z;
            hh[4] = *(ull*)&h2.x; hh[5] = *(ull*)&h2.z;
            hh[6] = *(ull*)&h3.x; hh[7] = *(ull*)&h3.z;

            ull acc[6];
            #pragma unroll
            for (int q = 0; q < 6; q++) {
                ull a = 0ull;
                #pragma unroll
                for (int i = 0; i < 8; i++) a = ffma2(w2[q][i], hh[i], a);
                acc[q] = a;
            }
            // paired butterfly reduce: outputs (2p, 2p+1) share one 16-wide tree
            #pragma unroll
            for (int p = 0; p < 3; p++) {
                float a0 = hsum2(acc[2*p]);
                float a1 = hsum2(acc[2*p+1]);
                float s0 = __shfl_xor_sync(0xffffffffu, a0, 16);
                float s1 = __shfl_xor_sync(0xffffffffu, a1, 16);
                float v = (lane < 16) ? (a0 + s0) : (a1 + s1);
                v += __shfl_xor_sync(0xffffffffu, v, 8);
                v += __shfl_xor_sync(0xffffffffu, v, 4);
                v += __shfl_xor_sync(0xffffffffu, v, 2);
                v += __shfl_xor_sync(0xffffffffu, v, 1);
                if (lane == 0)  y_s[rh*6 + 2*p][b]     = v + bhh_[2*p];
                if (lane == 16) y_s[rh*6 + 2*p + 1][b] = v + bhh_[2*p+1];
            }
        }
        __syncthreads();

        int nxt = cur ^ 1;
        if (tid < 64) {                   // gate epilogue: 4 units x 16 batches
            int u = tid >> 4, b = tid & 15;
            float r = sigm(xp_s[u][b]     + y_s[u][b]);
            float z = sigm(xp_s[4 + u][b] + y_s[4 + u][b]);
            float n = tanhf(xp_s[8 + u][b] + r * y_s[8 + u][b]);
            float hv = (1.f - z) * n + z * h_s[b][j0 + u];
            int j = j0 + u;
            __stcg(&g_hbuf[nxt][b * RNN + j], hv);
            g_hs[((size_t)b * TT + t) * RNN + j] = hv;
            __threadfence();
        }
        __syncthreads();
        if (tid == 0) {                   // grid barrier (monotone counter)
            unsigned tgt = (unsigned)(t + 1) * (unsigned)NBLK;
            atomicAdd(&g_cnt, 1u);
            while (*(volatile unsigned*)&g_cnt < tgt) { }
        }
        __syncthreads();
        cur = nxt;
    }
}

// ---------------- tiled fp32 GEMM (FFMA2 microkernel) ----------------
// C[m][n] = act(A[m][:] . W[n][:] + bias[n]);  M x 512 x 512, 64x64 tiles, BK=16
template<int ACT>
__global__ void __launch_bounds__(256) k_gemm(const float* __restrict__ A,
                                              const float* __restrict__ W,
                                              const float* __restrict__ bias,
                                              float* __restrict__ C) {
    __shared__ float As[16][68];
    __shared__ float Bs[16][68];
    int m0 = blockIdx.x * 64, n0 = blockIdx.y * 64;
    int tid = threadIdx.x;
    int tm = tid & 15, tn = tid >> 4;
    int lr = tid >> 2, lq = tid & 3;
    ull acc2[4][2];
    #pragma unroll
    for (int i = 0; i < 4; i++) { acc2[i][0] = 0ull; acc2[i][1] = 0ull; }

    for (int k0 = 0; k0 < 512; k0 += 16) {
        float4 av = *(const float4*)&A[(size_t)(m0 + lr) * 512 + k0 + 4 * lq];
        float4 bv = *(const float4*)&W[(size_t)(n0 + lr) * 512 + k0 + 4 * lq];
        __syncthreads();
        As[4*lq+0][lr] = av.x; As[4*lq+1][lr] = av.y; As[4*lq+2][lr] = av.z; As[4*lq+3][lr] = av.w;
        Bs[4*lq+0][lr] = bv.x; Bs[4*lq+1][lr] = bv.y; Bs[4*lq+2][lr] = bv.z; Bs[4*lq+3][lr] = bv.w;
        __syncthreads();
        #pragma unroll
        for (int k = 0; k < 16; k++) {
            float4 a = *(const float4*)&As[k][4 * tm];
            float4 b = *(const float4*)&Bs[k][4 * tn];
            ull b01 = *(ull*)&b.x, b23 = *(ull*)&b.z;
            ull ax = pack2(a.x, a.x), ay = pack2(a.y, a.y);
            ull az = pack2(a.z, a.z), aw = pack2(a.w, a.w);
            acc2[0][0] = ffma2(ax, b01, acc2[0][0]); acc2[0][1] = ffma2(ax, b23, acc2[0][1]);
            acc2[1][0] = ffma2(ay, b01, acc2[1][0]); acc2[1][1] = ffma2(ay, b23, acc2[1][1]);
            acc2[2][0] = ffma2(az, b01, acc2[2][0]); acc2[2][1] = ffma2(az, b23, acc2[2][1]);
            acc2[3][0] = ffma2(aw, b01, acc2[3][0]); acc2[3][1] = ffma2(aw, b23, acc2[3][1]);
        }
    }
    #pragma unroll
    for (int i = 0; i < 4; i++) {
        int m = m0 + 4 * tm + i;
        #pragma unroll
        for (int jj = 0; jj < 2; jj++) {
            float2 f = *(float2*)&acc2[i][jj];
            int n = n0 + 4 * tn + 2 * jj;
            float v0 = f.x + bias[n];
            float v1 = f.y + bias[n + 1];
            if (ACT == 1) { v0 = fmaxf(v0, 0.f); v1 = fmaxf(v1, 0.f); }
            C[(size_t)m * 512 + n]     = v0;
            C[(size_t)m * 512 + n + 1] = v1;
        }
    }
}

// ---------------- launch ----------------
extern "C" void kernel_launch(void* const* d_in, const int* in_sizes, int n_in,
                              void* d_out, int out_size) {
    const int*   x     = (const int*)  d_in[0];
    const float* mels  = (const float*)d_in[1];
    const float* up_k0 = (const float*)d_in[2];
    const float* up_k1 = (const float*)d_in[3];
    const float* up_k2 = (const float*)d_in[4];
    const float* w_ih  = (const float*)d_in[5];
    const float* w_hh  = (const float*)d_in[6];
    const float* b_ih  = (const float*)d_in[7];
    const float* b_hh  = (const float*)d_in[8];
    const float* fc1_w = (const float*)d_in[9];
    const float* fc1_b = (const float*)d_in[10];
    const float* fc2_w = (const float*)d_in[11];
    const float* fc2_b = (const float*)d_in[12];
    float* out = (float*)d_out;

    float *d_hs, *d_h1;
    cudaGetSymbolAddress((void**)&d_hs, g_hs);
    cudaGetSymbolAddress((void**)&d_h1, g_h1);

    k_init<<<64, 256>>>();
    k_woh<<<(NC * G3 + 255) / 256, 256>>>(w_ih);
    k_upsample<<<BB * FEAT, 512>>>(mels, up_k0, up_k1, up_k2);
    k_xproj<<<TT / 4, 256>>>(x, w_ih, b_ih);
    k_gru<<<NBLK, 256>>>(w_hh, b_hh);

    dim3 gg(BB * TT / 64, 512 / 64);
    k_gemm<1><<<gg, 256>>>(d_hs, fc1_w, fc1_b, d_h1);
    k_gemm<0><<<gg, 256>>>(d_h1, fc2_w, fc2_b, out);
}

// round 8
// speedup vs baseline: 1.1557x; 1.1557x over previous
#include <cuda_runtime.h>
#include <math.h>

#define BB    16
#define TT    3300
#define FEAT  80
#define NC    512
#define RNN   512
#define G3    1536
#define DIN   592
#define NBLK  128   // persistent GRU blocks

// ---------------- device scratch (no allocation allowed) ----------------
__device__ float    g_melsup[(size_t)BB * TT * FEAT];     // [b][t][f]
__device__ float    g_wohT[(size_t)NC * G3];              // [class][gate-row]
__device__ float    g_xproj[(size_t)TT * G3 * BB];        // [t][row][b] (includes b_ih)
__device__ float    g_hs[(size_t)BB * TT * RNN];          // GRU outputs
__device__ float    g_h1[(size_t)BB * TT * RNN];          // fc1 output
__device__ float    g_hbuf[2][BB * RNN];                  // ping-pong hidden state
__device__ unsigned g_cnt;                                // barrier counter

__device__ __forceinline__ float sigm(float x) { return 1.f / (1.f + __expf(-x)); }

// ---------------- init + one-hot table transpose (fused: launch #0) ----------------
__global__ void k_init_woh(const float* __restrict__ w_ih) {
    int idx = blockIdx.x * 256 + threadIdx.x;
    if (idx < 2 * BB * RNN) ((float*)g_hbuf)[idx] = 0.f;
    if (idx == 0) g_cnt = 0u;
    if (idx < NC * G3) {
        int g = idx % G3, c = idx / G3;
        g_wohT[(size_t)c * G3 + g] = __ldg(&w_ih[(size_t)g * DIN + c]);
    }
}

// ---------------- mel upsample: one block per (b,f)  (launch #1) ----------------
__global__ void k_upsample(const float* __restrict__ mels,
                           const float* __restrict__ k0,
                           const float* __restrict__ k1,
                           const float* __restrict__ k2) {
    int bf = blockIdx.x;
    int b = bf / FEAT, f = bf % FEAT;
    __shared__ float s0[16], s1[80], s2[400], c0[11], c1[11], c2[23];
    int tid = threadIdx.x;
    if (tid < 16) s0[tid] = mels[((size_t)b * FEAT + f) * 16 + tid];
    if (tid < 11) c0[tid] = k0[tid];
    if (tid < 11) c1[tid] = k1[tid];
    if (tid < 23) c2[tid] = k2[tid];
    __syncthreads();
    if (tid < 80) {
        float a = 0.f;
        #pragma unroll
        for (int u = 0; u < 11; u++) {
            int p = tid + u - 5;
            if (p >= 0 && p < 80) a += c0[u] * s0[p / 5];
        }
        s1[tid] = a;
    }
    __syncthreads();
    if (tid < 400) {
        float a = 0.f;
        #pragma unroll
        for (int u = 0; u < 11; u++) {
            int p = tid + u - 5;
            if (p >= 0 && p < 400) a += c1[u] * s1[p / 5];
        }
        s2[tid] = a;
    }
    __syncthreads();
    for (int i = tid; i < TT; i += blockDim.x) {
        int p = i + 550;
        float a = 0.f;
        #pragma unroll
        for (int u = 0; u < 23; u++) a += c2[u] * s2[(p + u - 11) / 11];
        g_melsup[((size_t)b * TT + i) * FEAT + f] = a;
    }
}

// ---------------- x_proj precompute: one block per t  (launch #2, R3 version) ----------------
__global__ void __launch_bounds__(256) k_xproj(const int* __restrict__ x,
                                               const float* __restrict__ w_ih,
                                               const float* __restrict__ b_ih) {
    int t = blockIdx.x;
    int tid = threadIdx.x;
    __shared__ float mel_s[BB][FEAT];
    __shared__ int   cls_s[BB];
    for (int i = tid; i < BB * FEAT; i += 256) {
        int b = i / FEAT, f = i % FEAT;
        mel_s[b][f] = g_melsup[((size_t)b * TT + t) * FEAT + f];
    }
    if (tid < BB) cls_s[tid] = x[(size_t)tid * TT + t];
    __syncthreads();

    for (int r = tid; r < G3; r += 256) {
        float acc[BB];
        float bi = b_ih[r];
        #pragma unroll
        for (int b = 0; b < BB; b++)
            acc[b] = bi + g_wohT[(size_t)cls_s[b] * G3 + r];
        const float* wrow = &w_ih[(size_t)r * DIN + NC];
        #pragma unroll 4
        for (int fq = 0; fq < FEAT / 4; fq++) {
            float4 w4 = __ldg((const float4*)wrow + fq);
            #pragma unroll
            for (int b = 0; b < BB; b++) {
                float4 m4 = *(const float4*)&mel_s[b][4 * fq];
                acc[b] += w4.x * m4.x + w4.y * m4.y + w4.z * m4.z + w4.w * m4.w;
            }
        }
        float* dst = &g_xproj[((size_t)t * G3 + r) * BB];
        #pragma unroll
        for (int q = 0; q < 4; q++)
            *(float4*)&dst[4 * q] = make_float4(acc[4*q], acc[4*q+1], acc[4*q+2], acc[4*q+3]);
    }
}

// ---------------- persistent GRU kernel (launch #3 -> gets ncu-profiled) ----------------
// R3 compute core (scalar FFMA, known-good) + scoped-atomic barrier + xp prefetch.
__global__ void __launch_bounds__(256, 1) k_gru(const float* __restrict__ w_hh,
                                                const float* __restrict__ b_hh) {
    int bk = blockIdx.x;
    int j0 = bk * 4;
    int tid = threadIdx.x;
    int wi = tid >> 5, lane = tid & 31;
    int rg = wi & 3;                      // rowgroup: 3 local rows each
    int bh = wi >> 2;                     // batch half: 8 batches each

    float w[3][16];
    float bhh_[3];
    #pragma unroll
    for (int q = 0; q < 3; q++) {
        int lr = rg * 3 + q;              // local row 0..11 == g*4+u
        int g = lr >> 2, u = lr & 3;
        int row = g * RNN + j0 + u;
        bhh_[q] = b_hh[row];
        #pragma unroll
        for (int i = 0; i < 4; i++) {
            float4 v = *(const float4*)&w_hh[(size_t)row * RNN + i * 128 + 4 * lane];
            w[q][4*i] = v.x; w[q][4*i+1] = v.y; w[q][4*i+2] = v.z; w[q][4*i+3] = v.w;
        }
    }

    __shared__ float h_s[BB][RNN];        // 32 KB
    __shared__ float y_s[12][BB];
    __shared__ float xp_s[12][BB];

    // xp prefetch state
    int plr = tid >> 4, pb = tid & 15;
    int prow = (plr >> 2) * RNN + j0 + (plr & 3);
    float xp_r = 0.f;
    if (tid < 192) xp_r = g_xproj[(size_t)prow * BB + pb];   // t=0

    unsigned* cnt_p = &g_cnt;
    int cur = 0;
    for (int t = 0; t < TT; t++) {
        if (tid < 192) xp_s[plr][pb] = xp_r;
        {                                 // stage h (L1-bypass: written by other SMs)
            const float4* src = (const float4*)g_hbuf[cur];
            float4* dst = (float4*)&h_s[0][0];
            #pragma unroll
            for (int i = 0; i < 8; i++) dst[tid + 256 * i] = __ldcg(src + tid + 256 * i);
        }
        __syncthreads();

        #pragma unroll 2
        for (int bi = 0; bi < 8; bi++) {
            int b = bh * 8 + bi;
            float4 h0 = *(const float4*)&h_s[b][4 * lane];
            float4 h1 = *(const float4*)&h_s[b][128 + 4 * lane];
            float4 h2 = *(const float4*)&h_s[b][256 + 4 * lane];
            float4 h3 = *(const float4*)&h_s[b][384 + 4 * lane];
            #pragma unroll
            for (int q = 0; q < 3; q++) {
                float a;
                a  = w[q][0]*h0.x + w[q][1]*h0.y + w[q][2]*h0.z + w[q][3]*h0.w;
                a += w[q][4]*h1.x + w[q][5]*h1.y + w[q][6]*h1.z + w[q][7]*h1.w;
                a += w[q][8]*h2.x + w[q][9]*h2.y + w[q][10]*h2.z + w[q][11]*h2.w;
                a += w[q][12]*h3.x + w[q][13]*h3.y + w[q][14]*h3.z + w[q][15]*h3.w;
                #pragma unroll
                for (int off = 16; off; off >>= 1) a += __shfl_xor_sync(0xffffffffu, a, off);
                if (lane == 0) y_s[rg * 3 + q][b] = a + bhh_[q];
            }
        }
        __syncthreads();

        int nxt = cur ^ 1;
        if (tid < 64) {                   // gate epilogue: 4 units x 16 batches
            int u = tid >> 4, b = tid & 15;
            float r = sigm(xp_s[u][b]     + y_s[u][b]);
            float z = sigm(xp_s[4 + u][b] + y_s[4 + u][b]);
            float n = tanhf(xp_s[8 + u][b] + r * y_s[8 + u][b]);
            float hv = (1.f - z) * n + z * h_s[b][j0 + u];
            int j = j0 + u;
            __stcg(&g_hbuf[nxt][b * RNN + j], hv);
            g_hs[((size_t)b * TT + t) * RNN + j] = hv;   // no per-step ordering needed
        }
        // prefetch next xp while epilogue/barrier runs
        if (tid < 192 && t + 1 < TT)
            xp_r = g_xproj[((size_t)(t + 1) * G3 + prow) * BB + pb];
        __syncthreads();                  // epilogue stores done before arrival
        if (tid == 0) {                   // scoped release/acquire grid barrier
            unsigned tgt = (unsigned)(t + 1) * (unsigned)NBLK;
            asm volatile("red.release.gpu.global.add.u32 [%0], 1;" :: "l"(cnt_p) : "memory");
            unsigned v;
            do {
                asm volatile("ld.acquire.gpu.global.u32 %0, [%1];" : "=r"(v) : "l"(cnt_p) : "memory");
            } while (v < tgt);
        }
        __syncthreads();
        cur = nxt;
    }
}

// ---------------- 3xTF32 tensor-core GEMM ----------------
// C[M=52800][512] = act(A[M][512] . W[512][512]^T + bias), BM=BN=64, BK=32.
// 8 warps: warp grid 2(m) x 4(n), warp tile 32x16 -> 2 mtiles x 2 ntiles of m16n8k8.
__device__ __forceinline__ void split_tf32(float v, unsigned &hi, unsigned &lo) {
    unsigned h;
    asm("cvt.rna.tf32.f32 %0, %1;" : "=r"(h) : "f"(v));
    float l = v - __uint_as_float(h);
    asm("cvt.rna.tf32.f32 %0, %1;" : "=r"(lo) : "f"(l));
    hi = h;
}

#define MMA_TF32(c, a, b) \
    asm volatile("mma.sync.aligned.m16n8k8.row.col.f32.tf32.tf32.f32 " \
        "{%0,%1,%2,%3}, {%4,%5,%6,%7}, {%8,%9}, {%0,%1,%2,%3};" \
        : "+f"(c[0]), "+f"(c[1]), "+f"(c[2]), "+f"(c[3]) \
        : "r"(a[0]), "r"(a[1]), "r"(a[2]), "r"(a[3]), "r"(b[0]), "r"(b[1]))

template<int ACT>
__global__ void __launch_bounds__(256) k_gemm_tc(const float* __restrict__ A,
                                                 const float* __restrict__ W,
                                                 const float* __restrict__ bias,
                                                 float* __restrict__ C) {
    __shared__ unsigned Ash[64][36], Asl[64][36];   // [m][k] stride 36 (conflict-free frags)
    __shared__ unsigned Bsh[64][36], Bsl[64][36];   // [n][k]
    const int m0 = blockIdx.x * 64, n0 = blockIdx.y * 64;
    const int tid = threadIdx.x;
    const int lane = tid & 31, wrp = tid >> 5;
    const int wm = wrp >> 2, wn = wrp & 3;          // 2 x 4 warp grid
    const int gid = lane >> 2, tig = lane & 3;

    float c[2][2][4];
    #pragma unroll
    for (int i = 0; i < 2; i++)
        #pragma unroll
        for (int j = 0; j < 2; j++)
            #pragma unroll
            for (int q = 0; q < 4; q++) c[i][j][q] = 0.f;

    for (int kc = 0; kc < 512; kc += 32) {
        __syncthreads();
        #pragma unroll
        for (int i = 0; i < 2; i++) {
            int p = tid + 256 * i;                   // 0..511
            int m = p >> 3, kq = p & 7;              // coalesced LDG
            float4 av = *(const float4*)&A[(size_t)(m0 + m) * 512 + kc + 4 * kq];
            float4 bv = *(const float4*)&W[(size_t)(n0 + m) * 512 + kc + 4 * kq];
            unsigned h0,l0,h1,l1,h2,l2,h3,l3;
            split_tf32(av.x, h0, l0); split_tf32(av.y, h1, l1);
            split_tf32(av.z, h2, l2); split_tf32(av.w, h3, l3);
            *(uint4*)&Ash[m][4 * kq] = make_uint4(h0, h1, h2, h3);
            *(uint4*)&Asl[m][4 * kq] = make_uint4(l0, l1, l2, l3);
            split_tf32(bv.x, h0, l0); split_tf32(bv.y, h1, l1);
            split_tf32(bv.z, h2, l2); split_tf32(bv.w, h3, l3);
            *(uint4*)&Bsh[m][4 * kq] = make_uint4(h0, h1, h2, h3);
            *(uint4*)&Bsl[m][4 * kq] = make_uint4(l0, l1, l2, l3);
        }
        __syncthreads();
        #pragma unroll
        for (int k8 = 0; k8 < 32; k8 += 8) {
            unsigned ah[2][4], al[2][4], bh2[2][2], bl2[2][2];
            #pragma unroll
            for (int mt = 0; mt < 2; mt++) {
                int m = wm * 32 + mt * 16 + gid;
                ah[mt][0] = Ash[m][k8 + tig];     ah[mt][1] = Ash[m + 8][k8 + tig];
                ah[mt][2] = Ash[m][k8 + 4 + tig]; ah[mt][3] = Ash[m + 8][k8 + 4 + tig];
                al[mt][0] = Asl[m][k8 + tig];     al[mt][1] = Asl[m + 8][k8 + tig];
                al[mt][2] = Asl[m][k8 + 4 + tig]; al[mt][3] = Asl[m + 8][k8 + 4 + tig];
            }
            #pragma unroll
            for (int nt = 0; nt < 2; nt++) {
                int n = wn * 16 + nt * 8 + gid;
                bh2[nt][0] = Bsh[n][k8 + tig]; bh2[nt][1] = Bsh[n][k8 + 4 + tig];
                bl2[nt][0] = Bsl[n][k8 + tig]; bl2[nt][1] = Bsl[n][k8 + 4 + tig];
            }
            #pragma unroll
            for (int mt = 0; mt < 2; mt++)
                #pragma unroll
                for (int nt = 0; nt < 2; nt++) {
                    MMA_TF32(c[mt][nt], ah[mt], bh2[nt]);
                    MMA_TF32(c[mt][nt], ah[mt], bl2[nt]);
                    MMA_TF32(c[mt][nt], al[mt], bh2[nt]);
                }
        }
    }

    #pragma unroll
    for (int mt = 0; mt < 2; mt++) {
        int m = m0 + wm * 32 + mt * 16 + gid;
        #pragma unroll
        for (int nt = 0; nt < 2; nt++) {
            int n = n0 + wn * 16 + nt * 8 + 2 * tig;
            float b0v = __ldg(&bias[n]), b1v = __ldg(&bias[n + 1]);
            float v0 = c[mt][nt][0] + b0v, v1 = c[mt][nt][1] + b1v;
            float v2 = c[mt][nt][2] + b0v, v3 = c[mt][nt][3] + b1v;
            if (ACT) {
                v0 = fmaxf(v0, 0.f); v1 = fmaxf(v1, 0.f);
                v2 = fmaxf(v2, 0.f); v3 = fmaxf(v3, 0.f);
            }
            *(float2*)&C[(size_t)m * 512 + n]       = make_float2(v0, v1);
            *(float2*)&C[(size_t)(m + 8) * 512 + n] = make_float2(v2, v3);
        }
    }
}

// ---------------- launch ----------------
extern "C" void kernel_launch(void* const* d_in, const int* in_sizes, int n_in,
                              void* d_out, int out_size) {
    const int*   x     = (const int*)  d_in[0];
    const float* mels  = (const float*)d_in[1];
    const float* up_k0 = (const float*)d_in[2];
    const float* up_k1 = (const float*)d_in[3];
    const float* up_k2 = (const float*)d_in[4];
    const float* w_ih  = (const float*)d_in[5];
    const float* w_hh  = (const float*)d_in[6];
    const float* b_ih  = (const float*)d_in[7];
    const float* b_hh  = (const float*)d_in[8];
    const float* fc1_w = (const float*)d_in[9];
    const float* fc1_b = (const float*)d_in[10];
    const float* fc2_w = (const float*)d_in[11];
    const float* fc2_b = (const float*)d_in[12];
    float* out = (float*)d_out;

    float *d_hs, *d_h1;
    cudaGetSymbolAddress((void**)&d_hs, g_hs);
    cudaGetSymbolAddress((void**)&d_h1, g_h1);

    k_init_woh<<<(NC * G3 + 255) / 256, 256>>>(w_ih);     // launch 0
    k_upsample<<<BB * FEAT, 512>>>(mels, up_k0, up_k1, up_k2);  // 1
    k_xproj<<<TT, 256>>>(x, w_ih, b_ih);                  // 2
    k_gru<<<NBLK, 256>>>(w_hh, b_hh);                     // 3  <- profiled slot

    dim3 gg(BB * TT / 64, 512 / 64);
    k_gemm_tc<1><<<gg, 256>>>(d_hs, fc1_w, fc1_b, d_h1);  // 4
    k_gemm_tc<0><<<gg, 256>>>(d_h1, fc2_w, fc2_b, out);   // 5
}